// round 8
// baseline (speedup 1.0000x reference)
#include <cuda_runtime.h>
#include <cuda_bf16.h>
#include <cstdint>

#define Sdim 2048
#define Bdim 32
#define Hdim 512
#define Gdim 2048   // 4*H
#define NCTA_REC 64

typedef unsigned long long ull;

// ---------------- scratch (module-load allocated) ----------------
__device__ float g_xg [(size_t)Sdim * Bdim * Gdim];               // [s*B+b][4H]
__device__ __align__(16) __nv_bfloat16 g_Ahi [(size_t)Sdim * Bdim * Hdim];
__device__ __align__(16) __nv_bfloat16 g_Alo [(size_t)Sdim * Bdim * Hdim];
__device__ __align__(16) __nv_bfloat16 g_h1hi[(size_t)Sdim * Bdim * Hdim];
__device__ __align__(16) __nv_bfloat16 g_h1lo[(size_t)Sdim * Bdim * Hdim];
__device__ __align__(16) __nv_bfloat16 g_Whi [2 * (size_t)Gdim * Hdim];
__device__ __align__(16) __nv_bfloat16 g_Wlo [2 * (size_t)Gdim * Hdim];
__device__ __align__(16) __nv_bfloat16 g_hb_hi[2][Bdim * Hdim];   // ping-pong h split
__device__ __align__(16) __nv_bfloat16 g_hb_lo[2][Bdim * Hdim];
__device__ unsigned g_cnt;
__device__ unsigned g_gen;

// ---------------- PTX helpers ----------------
__device__ __forceinline__ uint32_t smem_u32(const void* p) {
    uint32_t a;
    asm("{ .reg .u64 t; cvta.to.shared.u64 t, %1; cvt.u32.u64 %0, t; }" : "=r"(a) : "l"(p));
    return a;
}
#define CP_ASYNC16(dst, src) \
    asm volatile("cp.async.cg.shared.global [%0], [%1], 16;" :: "r"(dst), "l"(src))
#define CP_COMMIT() asm volatile("cp.async.commit_group;" ::: "memory")
#define CP_WAIT1()  asm volatile("cp.async.wait_group 1;" ::: "memory")
#define CP_WAIT0()  asm volatile("cp.async.wait_group 0;" ::: "memory")

__device__ __forceinline__ void ldm_x4(uint32_t* r, uint32_t addr) {
    asm volatile("ldmatrix.sync.aligned.m8n8.x4.shared.b16 {%0,%1,%2,%3}, [%4];"
                 : "=r"(r[0]), "=r"(r[1]), "=r"(r[2]), "=r"(r[3]) : "r"(addr));
}
__device__ __forceinline__ void mma_bf16(float* d, const uint32_t* a, const uint32_t* b) {
    asm volatile(
        "mma.sync.aligned.m16n8k16.row.col.f32.bf16.bf16.f32 "
        "{%0,%1,%2,%3}, {%4,%5,%6,%7}, {%8,%9}, {%0,%1,%2,%3};"
        : "+f"(d[0]), "+f"(d[1]), "+f"(d[2]), "+f"(d[3])
        : "r"(a[0]), "r"(a[1]), "r"(a[2]), "r"(a[3]), "r"(b[0]), "r"(b[1]));
}

// ---------------- grid barrier (validated R1/R4/R6; replay-safe) ----------------
__device__ __forceinline__ void grid_barrier() {
    __syncthreads();
    if (threadIdx.x == 0) {
        __threadfence();
        unsigned gen = *(volatile unsigned*)&g_gen;
        unsigned old = atomicAdd(&g_cnt, 1u);
        if (old == gridDim.x - 1) {
            atomicExch(&g_cnt, 0u);
            __threadfence();
            atomicAdd(&g_gen, 1u);
        } else {
            while (*(volatile unsigned*)&g_gen == gen) { __nanosleep(32); }
        }
        __threadfence();
    }
    __syncthreads();
}

// ---------------- fp32 -> bf16 hi/lo split ----------------
__device__ __forceinline__ void split4(float4 v, ull& hi, ull& lo) {
    union { __nv_bfloat16 h[4]; ull u; } H, L;
    float f[4] = {v.x, v.y, v.z, v.w};
#pragma unroll
    for (int i = 0; i < 4; i++) {
        __nv_bfloat16 a = __float2bfloat16_rn(f[i]);
        H.h[i] = a;
        L.h[i] = __float2bfloat16_rn(f[i] - __bfloat162float(a));
    }
    hi = H.u; lo = L.u;
}

// X[b][s][k] -> g_Ahi/g_Alo[(s*B+b)][k]
__global__ __launch_bounds__(256) void conv_x_kernel(const float* __restrict__ X) {
    size_t i = (size_t)blockIdx.x * 256 + threadIdx.x;
    int row = (int)(i >> 7);
    int c4  = (int)(i & 127);
    int b = row & 31, s = row >> 5;
    float4 v = __ldg((const float4*)(X + ((size_t)b * Sdim + s) * Hdim + c4 * 4));
    ull hi, lo;
    split4(v, hi, lo);
    *(ull*)(g_Ahi + (size_t)row * Hdim + c4 * 4) = hi;
    *(ull*)(g_Alo + (size_t)row * Hdim + c4 * 4) = lo;
}

// Wih[2][4H][H] -> g_Whi/g_Wlo
__global__ __launch_bounds__(256) void conv_w_kernel(const float* __restrict__ W) {
    size_t i = (size_t)blockIdx.x * 256 + threadIdx.x;
    float4 v = __ldg((const float4*)W + i);
    ull hi, lo;
    split4(v, hi, lo);
    *(ull*)(g_Whi + i * 4) = hi;
    *(ull*)(g_Wlo + i * 4) = lo;
}

// ---------------- mma.sync split-bf16 GEMM (validated R4) ----------------
#define TSTRIDE 80
#define MAT_B   (128 * TSTRIDE)
#define STAGE_B (4 * MAT_B)

__global__ __launch_bounds__(256, 1) void gemm_mma_kernel(
    int src_h1, int layer,
    const float* __restrict__ bih, const float* __restrict__ bhh)
{
    extern __shared__ char smem[];
    uint32_t sb = smem_u32(smem);
    int tid = threadIdx.x, wid = tid >> 5, lane = tid & 31;
    int col0 = blockIdx.x * 128;
    int row0 = blockIdx.y * 128;
    int wm = wid & 1, wn = wid >> 1;

    const __nv_bfloat16* a0p = (src_h1 ? g_h1hi : g_Ahi) + (size_t)row0 * Hdim;
    const __nv_bfloat16* a1p = (src_h1 ? g_h1lo : g_Alo) + (size_t)row0 * Hdim;
    const __nv_bfloat16* w0p = g_Whi + (size_t)layer * Gdim * Hdim + (size_t)col0 * Hdim;
    const __nv_bfloat16* w1p = g_Wlo + (size_t)layer * Gdim * Hdim + (size_t)col0 * Hdim;

    int ldr  = tid >> 2;
    int ldkc = tid & 3;

#define PREFETCH(stg, k0)                                                         \
    do {                                                                          \
        _Pragma("unroll")                                                         \
        for (int m = 0; m < 4; m++) {                                             \
            const __nv_bfloat16* mp = (m == 0 ? a0p : m == 1 ? a1p :              \
                                       m == 2 ? w0p : w1p);                       \
            _Pragma("unroll")                                                     \
            for (int i = 0; i < 2; i++) {                                         \
                int r = ldr + i * 64;                                             \
                uint32_t dst = sb + (stg) * STAGE_B + m * MAT_B +                 \
                               r * TSTRIDE + ldkc * 16;                           \
                const void* srcp = mp + (size_t)r * Hdim + (k0) + ldkc * 8;       \
                CP_ASYNC16(dst, srcp);                                            \
            }                                                                     \
        }                                                                         \
        CP_COMMIT();                                                              \
    } while (0)

    float acc[4][4][4];
#pragma unroll
    for (int i = 0; i < 4; i++)
#pragma unroll
        for (int j = 0; j < 4; j++)
#pragma unroll
            for (int k = 0; k < 4; k++) acc[i][j][k] = 0.0f;

    PREFETCH(0, 0);
    PREFETCH(1, 32);

    int tile = lane >> 3, trow = lane & 7;

    for (int kt = 0; kt < 16; kt++) {
        if (kt == 15) CP_WAIT0(); else CP_WAIT1();
        __syncthreads();
        uint32_t base = sb + (kt & 1) * STAGE_B;

#pragma unroll
        for (int ks = 0; ks < 2; ks++) {
            uint32_t ahi[4][4], alo[4][4];
#pragma unroll
            for (int mf = 0; mf < 4; mf++) {
                int row = wm * 64 + mf * 16 + (tile & 1) * 8 + trow;
                int col = ks * 16 + (tile >> 1) * 8;
                ldm_x4(ahi[mf], base + 0 * MAT_B + row * TSTRIDE + col * 2);
                ldm_x4(alo[mf], base + 1 * MAT_B + row * TSTRIDE + col * 2);
            }
            uint32_t bhi[4][2], blo[4][2];
#pragma unroll
            for (int p = 0; p < 2; p++) {
                int rn = wn * 32 + p * 16 + (tile >> 1) * 8 + trow;
                int ck = ks * 16 + (tile & 1) * 8;
                uint32_t r4[4];
                ldm_x4(r4, base + 2 * MAT_B + rn * TSTRIDE + ck * 2);
                bhi[2*p][0] = r4[0]; bhi[2*p][1] = r4[1];
                bhi[2*p+1][0] = r4[2]; bhi[2*p+1][1] = r4[3];
                ldm_x4(r4, base + 3 * MAT_B + rn * TSTRIDE + ck * 2);
                blo[2*p][0] = r4[0]; blo[2*p][1] = r4[1];
                blo[2*p+1][0] = r4[2]; blo[2*p+1][1] = r4[3];
            }
#pragma unroll
            for (int mf = 0; mf < 4; mf++)
#pragma unroll
                for (int nf = 0; nf < 4; nf++) {
                    mma_bf16(acc[mf][nf], ahi[mf], bhi[nf]);
                    mma_bf16(acc[mf][nf], ahi[mf], blo[nf]);
                    mma_bf16(acc[mf][nf], alo[mf], bhi[nf]);
                }
        }
        __syncthreads();
        if (kt < 14) PREFETCH(kt & 1, (kt + 2) * 32);
    }

#pragma unroll
    for (int mf = 0; mf < 4; mf++) {
        int r0 = row0 + wm * 64 + mf * 16 + (lane >> 2);
#pragma unroll
        for (int nf = 0; nf < 4; nf++) {
            int cb = col0 + wn * 32 + nf * 8 + 2 * (lane & 3);
            float b0v = __ldg(&bih[cb])     + __ldg(&bhh[cb]);
            float b1v = __ldg(&bih[cb + 1]) + __ldg(&bhh[cb + 1]);
            *(float2*)&g_xg[(size_t)r0 * Gdim + cb] =
                make_float2(acc[mf][nf][0] + b0v, acc[mf][nf][1] + b1v);
            *(float2*)&g_xg[(size_t)(r0 + 8) * Gdim + cb] =
                make_float2(acc[mf][nf][2] + b0v, acc[mf][nf][3] + b1v);
        }
    }
#undef PREFETCH
}

// ---------------- persistent recurrence on tensor cores ----------------
// 64 CTAs x 256 threads. CTA owns 8 hidden units (32 gate cols).
// Whh B-frags in registers (split bf16); h staged split via cp.async each step.
// 8-warp k-split (64 each); smem reduction; 256 threads do activations.
#define RSTRIDE 1040                 // bytes per smem bf16 row of 512 (+8 pad)
#define RED_OFF (64 * RSTRIDE)       // 66560
#define RED_LEN 33                   // floats per red row

__global__ __launch_bounds__(256, 1) void lstm_recur_mma(
    const float* __restrict__ Whh, float* __restrict__ hseq,
    int out_bsh, float* __restrict__ hTo, float* __restrict__ cTo)
{
    extern __shared__ char sm[];
    uint32_t sb = smem_u32(sm);
    uint32_t sHhi = sb;                       // [32 rows] (also W-hi staging at init)
    uint32_t sHlo = sb + 32 * RSTRIDE;        // [32 rows] (also W-lo staging at init)
    float* red = (float*)(sm + RED_OFF);      // [8][32][RED_LEN]

    int tid = threadIdx.x, wid = tid >> 5, lane = tid & 31;
    int b  = tid & 31;
    int jj = tid >> 5;          // 0..7: hidden unit within CTA
    int j0 = blockIdx.x * 8;

    // stage Whh (split bf16) into the H area: row r = q*8 + j  <-  Whh[q*512 + j0 + j]
    for (int idx = tid; idx < 32 * 128; idx += 256) {
        int r = idx >> 7, c4 = idx & 127;
        int q = r >> 3, j = r & 7;
        float4 v = __ldg((const float4*)(Whh + (size_t)(q * Hdim + j0 + j) * Hdim + c4 * 4));
        ull hi, lo;
        split4(v, hi, lo);
        *(ull*)(sm + r * RSTRIDE + c4 * 8) = hi;
        *(ull*)(sm + 32 * RSTRIDE + r * RSTRIDE + c4 * 8) = lo;
    }
    // h(0) = 0 (64 CTAs x 256 threads cover all 32x512)
    g_hb_hi[0][b * Hdim + j0 + jj] = __float2bfloat16(0.0f);
    g_hb_lo[0][b * Hdim + j0 + jj] = __float2bfloat16(0.0f);
    __syncthreads();

    // preload B fragments: warp w owns k in [w*64, w*64+64); N=32 gate cols
    int kbase = wid * 64;
    int tile = lane >> 3, trow = lane & 7;
    uint32_t bhi[4][4][2], blo[4][4][2];
#pragma unroll
    for (int kt = 0; kt < 4; kt++) {
#pragma unroll
        for (int p = 0; p < 2; p++) {
            int rn = p * 16 + (tile >> 1) * 8 + trow;
            int ck = kbase + kt * 16 + (tile & 1) * 8;
            uint32_t r4[4];
            ldm_x4(r4, sHhi + rn * RSTRIDE + ck * 2);
            bhi[kt][2*p][0] = r4[0]; bhi[kt][2*p][1] = r4[1];
            bhi[kt][2*p+1][0] = r4[2]; bhi[kt][2*p+1][1] = r4[3];
            ldm_x4(r4, sHlo + rn * RSTRIDE + ck * 2);
            blo[kt][2*p][0] = r4[0]; blo[kt][2*p][1] = r4[1];
            blo[kt][2*p+1][0] = r4[2]; blo[kt][2*p+1][1] = r4[3];
        }
    }
    grid_barrier();   // h(0) visible; W-frag reads done before H reuses the area

    float c_st = 0.0f;
    const float* xg_base = g_xg + (size_t)b * Gdim + (j0 + jj);

    for (int t = 0; t < Sdim; t++) {
        int cur = t & 1;
        float x_i = __ldg(xg_base + 0 * Hdim);
        float x_f = __ldg(xg_base + 1 * Hdim);
        float x_g = __ldg(xg_base + 2 * Hdim);
        float x_o = __ldg(xg_base + 3 * Hdim);

        // stage h(t-1) split: 2 x 32KB -> smem (barrier at loop end published it)
        const char* srchi = (const char*)g_hb_hi[cur];
        const char* srclo = (const char*)g_hb_lo[cur];
#pragma unroll
        for (int i = 0; i < 8; i++) {
            int idx = tid + i * 256;          // 0..2047 (16B chunks)
            int r = idx >> 6, ch = idx & 63;
            CP_ASYNC16(sHhi + r * RSTRIDE + ch * 16, srchi + idx * 16);
            CP_ASYNC16(sHlo + r * RSTRIDE + ch * 16, srclo + idx * 16);
        }
        CP_COMMIT();
        CP_WAIT0();
        __syncthreads();

        // MMA: [32 x 64-slice] x [64-slice x 32] partials
        float acc[2][4][4];
#pragma unroll
        for (int i = 0; i < 2; i++)
#pragma unroll
            for (int j = 0; j < 4; j++)
#pragma unroll
                for (int k = 0; k < 4; k++) acc[i][j][k] = 0.0f;

#pragma unroll
        for (int kt = 0; kt < 4; kt++) {
            int colb = kbase + kt * 16 + (tile >> 1) * 8;
            uint32_t ahi[2][4], alo[2][4];
#pragma unroll
            for (int mf = 0; mf < 2; mf++) {
                int row = mf * 16 + (tile & 1) * 8 + trow;
                ldm_x4(ahi[mf], sHhi + row * RSTRIDE + colb * 2);
                ldm_x4(alo[mf], sHlo + row * RSTRIDE + colb * 2);
            }
#pragma unroll
            for (int mf = 0; mf < 2; mf++)
#pragma unroll
                for (int nf = 0; nf < 4; nf++) {
                    mma_bf16(acc[mf][nf], ahi[mf], bhi[kt][nf]);
                    mma_bf16(acc[mf][nf], ahi[mf], blo[kt][nf]);
                    mma_bf16(acc[mf][nf], alo[mf], bhi[kt][nf]);
                }
        }

        // per-warp partials -> red[wid][m 0..31][n 0..31]
#pragma unroll
        for (int mf = 0; mf < 2; mf++)
#pragma unroll
            for (int nf = 0; nf < 4; nf++) {
                int row = mf * 16 + (lane >> 2);
                int col = nf * 8 + (lane & 3) * 2;
                float* p0 = red + ((wid * 32 + row) * RED_LEN + col);
                p0[0] = acc[mf][nf][0]; p0[1] = acc[mf][nf][1];
                float* p1 = red + ((wid * 32 + row + 8) * RED_LEN + col);
                p1[0] = acc[mf][nf][2]; p1[1] = acc[mf][nf][3];
            }
        __syncthreads();

        // all 256 threads: (b, jj) activation + state update
        {
            float di = x_i, df = x_f, dg = x_g, do_ = x_o;
#pragma unroll
            for (int w = 0; w < 8; w++) {
                const float* rr = red + (w * 32 + b) * RED_LEN;
                di  += rr[0 * 8 + jj];
                df  += rr[1 * 8 + jj];
                dg  += rr[2 * 8 + jj];
                do_ += rr[3 * 8 + jj];
            }
            float ig = 1.0f / (1.0f + __expf(-di));
            float fg = 1.0f / (1.0f + __expf(-df));
            float gg = tanhf(dg);
            float og = 1.0f / (1.0f + __expf(-do_));
            c_st = fg * c_st + ig * gg;
            float h = og * tanhf(c_st);

            __nv_bfloat16 hh = __float2bfloat16_rn(h);
            __nv_bfloat16 hl = __float2bfloat16_rn(h - __bfloat162float(hh));
            g_hb_hi[cur ^ 1][b * Hdim + j0 + jj] = hh;
            g_hb_lo[cur ^ 1][b * Hdim + j0 + jj] = hl;
            if (out_bsh) {
                hseq[((size_t)b * Sdim + t) * Hdim + j0 + jj] = h;
                if (hTo && t == Sdim - 1) {
                    hTo[b * Hdim + j0 + jj] = h;
                    cTo[b * Hdim + j0 + jj] = c_st;
                }
            } else {
                size_t r = ((size_t)t * Bdim + b) * Hdim + j0 + jj;
                g_h1hi[r] = hh;
                g_h1lo[r] = hl;
            }
        }
        grid_barrier();   // publishes h(t); isolates red / sH reuse

        xg_base += (size_t)Bdim * Gdim;
    }
}

// ---------------- launch ----------------
extern "C" void kernel_launch(void* const* d_in, const int* in_sizes, int n_in,
                              void* d_out, int out_size) {
    (void)in_sizes; (void)n_in;
    const float* X   = (const float*)d_in[0];
    const float* Wih = (const float*)d_in[1];
    const float* Whh = (const float*)d_in[2];
    const float* bih = (const float*)d_in[3];
    const float* bhh = (const float*)d_in[4];
    float* out = (float*)d_out;

    size_t ht_elems = (size_t)Bdim * Sdim * Hdim;
    float* hTo = nullptr; float* cTo = nullptr;
    if ((size_t)out_size >= ht_elems + 2 * (size_t)Bdim * Hdim) {
        hTo = out + ht_elems;
        cTo = hTo + (size_t)Bdim * Hdim;
    }

    const int smem_rec  = RED_OFF + 8 * 32 * RED_LEN * 4;   // 66560 + 33792 = 100352
    const int smem_gemm = 2 * STAGE_B;                      // 81920
    cudaFuncSetAttribute(lstm_recur_mma,
                         cudaFuncAttributeMaxDynamicSharedMemorySize, smem_rec);
    cudaFuncSetAttribute(gemm_mma_kernel,
                         cudaFuncAttributeMaxDynamicSharedMemorySize, smem_gemm);

    conv_w_kernel<<<2048, 256>>>(Wih);
    conv_x_kernel<<<32768, 256>>>(X);

    dim3 ggrid(Gdim / 128, (Sdim * Bdim) / 128);   // (16, 512)

    // Layer 0
    gemm_mma_kernel<<<ggrid, 256, smem_gemm>>>(0, 0, bih, bhh);
    lstm_recur_mma<<<NCTA_REC, 256, smem_rec>>>(Whh, nullptr, 0, nullptr, nullptr);
    // Layer 1
    gemm_mma_kernel<<<ggrid, 256, smem_gemm>>>(1, 1, bih + Gdim, bhh + Gdim);
    lstm_recur_mma<<<NCTA_REC, 256, smem_rec>>>(Whh + (size_t)Gdim * Hdim,
                                                out, 1, hTo, cTo);
}

// round 9
// speedup vs baseline: 1.0025x; 1.0025x over previous
#include <cuda_runtime.h>
#include <cuda_bf16.h>
#include <cstdint>

#define Sdim 2048
#define Bdim 32
#define Hdim 512
#define Gdim 2048   // 4*H
#define NCTA_REC 64

typedef unsigned long long ull;

// ---------------- scratch (module-load allocated) ----------------
__device__ float g_xg [(size_t)Sdim * Bdim * Gdim];               // [s*B+b][4H]
__device__ __align__(16) __nv_bfloat16 g_Ahi [(size_t)Sdim * Bdim * Hdim];
__device__ __align__(16) __nv_bfloat16 g_Alo [(size_t)Sdim * Bdim * Hdim];
__device__ __align__(16) __nv_bfloat16 g_h1hi[(size_t)Sdim * Bdim * Hdim];
__device__ __align__(16) __nv_bfloat16 g_h1lo[(size_t)Sdim * Bdim * Hdim];
__device__ __align__(16) __nv_bfloat16 g_Whi [2 * (size_t)Gdim * Hdim];
__device__ __align__(16) __nv_bfloat16 g_Wlo [2 * (size_t)Gdim * Hdim];
__device__ __align__(16) __nv_bfloat16 g_hb_hi[2][Bdim * Hdim];   // ping-pong h split
__device__ __align__(16) __nv_bfloat16 g_hb_lo[2][Bdim * Hdim];
__device__ unsigned g_cnt;
__device__ unsigned g_gen;

// ---------------- PTX helpers ----------------
__device__ __forceinline__ uint32_t smem_u32(const void* p) {
    uint32_t a;
    asm("{ .reg .u64 t; cvta.to.shared.u64 t, %1; cvt.u32.u64 %0, t; }" : "=r"(a) : "l"(p));
    return a;
}
#define CP_ASYNC16(dst, src) \
    asm volatile("cp.async.cg.shared.global [%0], [%1], 16;" :: "r"(dst), "l"(src))
#define CP_COMMIT() asm volatile("cp.async.commit_group;" ::: "memory")
#define CP_WAIT1()  asm volatile("cp.async.wait_group 1;" ::: "memory")
#define CP_WAIT0()  asm volatile("cp.async.wait_group 0;" ::: "memory")

__device__ __forceinline__ void ldm_x4(uint32_t* r, uint32_t addr) {
    asm volatile("ldmatrix.sync.aligned.m8n8.x4.shared.b16 {%0,%1,%2,%3}, [%4];"
                 : "=r"(r[0]), "=r"(r[1]), "=r"(r[2]), "=r"(r[3]) : "r"(addr));
}
__device__ __forceinline__ void mma_bf16(float* d, const uint32_t* a, const uint32_t* b) {
    asm volatile(
        "mma.sync.aligned.m16n8k16.row.col.f32.bf16.bf16.f32 "
        "{%0,%1,%2,%3}, {%4,%5,%6,%7}, {%8,%9}, {%0,%1,%2,%3};"
        : "+f"(d[0]), "+f"(d[1]), "+f"(d[2]), "+f"(d[3])
        : "r"(a[0]), "r"(a[1]), "r"(a[2]), "r"(a[3]), "r"(b[0]), "r"(b[1]));
}

// ---------------- grid barrier (validated R1/R4/R6; replay-safe) ----------------
__device__ __forceinline__ void grid_barrier() {
    __syncthreads();
    if (threadIdx.x == 0) {
        __threadfence();
        unsigned gen = *(volatile unsigned*)&g_gen;
        unsigned old = atomicAdd(&g_cnt, 1u);
        if (old == gridDim.x - 1) {
            atomicExch(&g_cnt, 0u);
            __threadfence();
            atomicAdd(&g_gen, 1u);
        } else {
            while (*(volatile unsigned*)&g_gen == gen) { __nanosleep(32); }
        }
        __threadfence();
    }
    __syncthreads();
}

// ---------------- fp32 -> bf16 hi/lo split ----------------
__device__ __forceinline__ void split4(float4 v, ull& hi, ull& lo) {
    union { __nv_bfloat16 h[4]; ull u; } H, L;
    float f[4] = {v.x, v.y, v.z, v.w};
#pragma unroll
    for (int i = 0; i < 4; i++) {
        __nv_bfloat16 a = __float2bfloat16_rn(f[i]);
        H.h[i] = a;
        L.h[i] = __float2bfloat16_rn(f[i] - __bfloat162float(a));
    }
    hi = H.u; lo = L.u;
}

// X[b][s][k] -> g_Ahi/g_Alo[(s*B+b)][k]
__global__ __launch_bounds__(256) void conv_x_kernel(const float* __restrict__ X) {
    size_t i = (size_t)blockIdx.x * 256 + threadIdx.x;
    int row = (int)(i >> 7);
    int c4  = (int)(i & 127);
    int b = row & 31, s = row >> 5;
    float4 v = __ldg((const float4*)(X + ((size_t)b * Sdim + s) * Hdim + c4 * 4));
    ull hi, lo;
    split4(v, hi, lo);
    *(ull*)(g_Ahi + (size_t)row * Hdim + c4 * 4) = hi;
    *(ull*)(g_Alo + (size_t)row * Hdim + c4 * 4) = lo;
}

// Wih[2][4H][H] -> g_Whi/g_Wlo
__global__ __launch_bounds__(256) void conv_w_kernel(const float* __restrict__ W) {
    size_t i = (size_t)blockIdx.x * 256 + threadIdx.x;
    float4 v = __ldg((const float4*)W + i);
    ull hi, lo;
    split4(v, hi, lo);
    *(ull*)(g_Whi + i * 4) = hi;
    *(ull*)(g_Wlo + i * 4) = lo;
}

// ---------------- mma.sync split-bf16 GEMM (validated R4) ----------------
#define TSTRIDE 80
#define MAT_B   (128 * TSTRIDE)
#define STAGE_B (4 * MAT_B)

__global__ __launch_bounds__(256, 1) void gemm_mma_kernel(
    int src_h1, int layer,
    const float* __restrict__ bih, const float* __restrict__ bhh)
{
    extern __shared__ char smem[];
    uint32_t sb = smem_u32(smem);
    int tid = threadIdx.x, wid = tid >> 5, lane = tid & 31;
    int col0 = blockIdx.x * 128;
    int row0 = blockIdx.y * 128;
    int wm = wid & 1, wn = wid >> 1;

    const __nv_bfloat16* a0p = (src_h1 ? g_h1hi : g_Ahi) + (size_t)row0 * Hdim;
    const __nv_bfloat16* a1p = (src_h1 ? g_h1lo : g_Alo) + (size_t)row0 * Hdim;
    const __nv_bfloat16* w0p = g_Whi + (size_t)layer * Gdim * Hdim + (size_t)col0 * Hdim;
    const __nv_bfloat16* w1p = g_Wlo + (size_t)layer * Gdim * Hdim + (size_t)col0 * Hdim;

    int ldr  = tid >> 2;
    int ldkc = tid & 3;

#define PREFETCH(stg, k0)                                                         \
    do {                                                                          \
        _Pragma("unroll")                                                         \
        for (int m = 0; m < 4; m++) {                                             \
            const __nv_bfloat16* mp = (m == 0 ? a0p : m == 1 ? a1p :              \
                                       m == 2 ? w0p : w1p);                       \
            _Pragma("unroll")                                                     \
            for (int i = 0; i < 2; i++) {                                         \
                int r = ldr + i * 64;                                             \
                uint32_t dst = sb + (stg) * STAGE_B + m * MAT_B +                 \
                               r * TSTRIDE + ldkc * 16;                           \
                const void* srcp = mp + (size_t)r * Hdim + (k0) + ldkc * 8;       \
                CP_ASYNC16(dst, srcp);                                            \
            }                                                                     \
        }                                                                         \
        CP_COMMIT();                                                              \
    } while (0)

    float acc[4][4][4];
#pragma unroll
    for (int i = 0; i < 4; i++)
#pragma unroll
        for (int j = 0; j < 4; j++)
#pragma unroll
            for (int k = 0; k < 4; k++) acc[i][j][k] = 0.0f;

    PREFETCH(0, 0);
    PREFETCH(1, 32);

    int tile = lane >> 3, trow = lane & 7;

    for (int kt = 0; kt < 16; kt++) {
        if (kt == 15) CP_WAIT0(); else CP_WAIT1();
        __syncthreads();
        uint32_t base = sb + (kt & 1) * STAGE_B;

#pragma unroll
        for (int ks = 0; ks < 2; ks++) {
            uint32_t ahi[4][4], alo[4][4];
#pragma unroll
            for (int mf = 0; mf < 4; mf++) {
                int row = wm * 64 + mf * 16 + (tile & 1) * 8 + trow;
                int col = ks * 16 + (tile >> 1) * 8;
                ldm_x4(ahi[mf], base + 0 * MAT_B + row * TSTRIDE + col * 2);
                ldm_x4(alo[mf], base + 1 * MAT_B + row * TSTRIDE + col * 2);
            }
            uint32_t bhi[4][2], blo[4][2];
#pragma unroll
            for (int p = 0; p < 2; p++) {
                int rn = wn * 32 + p * 16 + (tile >> 1) * 8 + trow;
                int ck = ks * 16 + (tile & 1) * 8;
                uint32_t r4[4];
                ldm_x4(r4, base + 2 * MAT_B + rn * TSTRIDE + ck * 2);
                bhi[2*p][0] = r4[0]; bhi[2*p][1] = r4[1];
                bhi[2*p+1][0] = r4[2]; bhi[2*p+1][1] = r4[3];
                ldm_x4(r4, base + 3 * MAT_B + rn * TSTRIDE + ck * 2);
                blo[2*p][0] = r4[0]; blo[2*p][1] = r4[1];
                blo[2*p+1][0] = r4[2]; blo[2*p+1][1] = r4[3];
            }
#pragma unroll
            for (int mf = 0; mf < 4; mf++)
#pragma unroll
                for (int nf = 0; nf < 4; nf++) {
                    mma_bf16(acc[mf][nf], ahi[mf], bhi[nf]);
                    mma_bf16(acc[mf][nf], ahi[mf], blo[nf]);
                    mma_bf16(acc[mf][nf], alo[mf], bhi[nf]);
                }
        }
        __syncthreads();
        if (kt < 14) PREFETCH(kt & 1, (kt + 2) * 32);
    }

#pragma unroll
    for (int mf = 0; mf < 4; mf++) {
        int r0 = row0 + wm * 64 + mf * 16 + (lane >> 2);
#pragma unroll
        for (int nf = 0; nf < 4; nf++) {
            int cb = col0 + wn * 32 + nf * 8 + 2 * (lane & 3);
            float b0v = __ldg(&bih[cb])     + __ldg(&bhh[cb]);
            float b1v = __ldg(&bih[cb + 1]) + __ldg(&bhh[cb + 1]);
            *(float2*)&g_xg[(size_t)r0 * Gdim + cb] =
                make_float2(acc[mf][nf][0] + b0v, acc[mf][nf][1] + b1v);
            *(float2*)&g_xg[(size_t)(r0 + 8) * Gdim + cb] =
                make_float2(acc[mf][nf][2] + b0v, acc[mf][nf][3] + b1v);
        }
    }
#undef PREFETCH
}

// ---------------- persistent recurrence on tensor cores ----------------
// 64 CTAs x 256 threads. CTA owns 8 hidden units (32 gate cols).
// Whh B-frags in registers (split bf16); h staged split via cp.async each step.
// 8-warp k-split (64 each); smem reduction; 256 threads do activations.
#define RSTRIDE 1040                 // bytes per smem bf16 row of 512 (+8 pad)
#define RED_OFF (64 * RSTRIDE)       // 66560
#define RED_LEN 33                   // floats per red row

__global__ __launch_bounds__(256, 1) void lstm_recur_mma(
    const float* __restrict__ Whh, float* __restrict__ hseq,
    int out_bsh, float* __restrict__ hTo, float* __restrict__ cTo)
{
    extern __shared__ char sm[];
    uint32_t sb = smem_u32(sm);
    uint32_t sHhi = sb;                       // [32 rows] (also W-hi staging at init)
    uint32_t sHlo = sb + 32 * RSTRIDE;        // [32 rows] (also W-lo staging at init)
    float* red = (float*)(sm + RED_OFF);      // [8][32][RED_LEN]

    int tid = threadIdx.x, wid = tid >> 5, lane = tid & 31;
    int b  = tid & 31;
    int jj = tid >> 5;          // 0..7: hidden unit within CTA
    int j0 = blockIdx.x * 8;

    // stage Whh (split bf16) into the H area: row r = q*8 + j  <-  Whh[q*512 + j0 + j]
    for (int idx = tid; idx < 32 * 128; idx += 256) {
        int r = idx >> 7, c4 = idx & 127;
        int q = r >> 3, j = r & 7;
        float4 v = __ldg((const float4*)(Whh + (size_t)(q * Hdim + j0 + j) * Hdim + c4 * 4));
        ull hi, lo;
        split4(v, hi, lo);
        *(ull*)(sm + r * RSTRIDE + c4 * 8) = hi;
        *(ull*)(sm + 32 * RSTRIDE + r * RSTRIDE + c4 * 8) = lo;
    }
    // h(0) = 0 (64 CTAs x 256 threads cover all 32x512)
    g_hb_hi[0][b * Hdim + j0 + jj] = __float2bfloat16(0.0f);
    g_hb_lo[0][b * Hdim + j0 + jj] = __float2bfloat16(0.0f);
    __syncthreads();

    // preload B fragments: warp w owns k in [w*64, w*64+64); N=32 gate cols
    int kbase = wid * 64;
    int tile = lane >> 3, trow = lane & 7;
    uint32_t bhi[4][4][2], blo[4][4][2];
#pragma unroll
    for (int kt = 0; kt < 4; kt++) {
#pragma unroll
        for (int p = 0; p < 2; p++) {
            int rn = p * 16 + (tile >> 1) * 8 + trow;
            int ck = kbase + kt * 16 + (tile & 1) * 8;
            uint32_t r4[4];
            ldm_x4(r4, sHhi + rn * RSTRIDE + ck * 2);
            bhi[kt][2*p][0] = r4[0]; bhi[kt][2*p][1] = r4[1];
            bhi[kt][2*p+1][0] = r4[2]; bhi[kt][2*p+1][1] = r4[3];
            ldm_x4(r4, sHlo + rn * RSTRIDE + ck * 2);
            blo[kt][2*p][0] = r4[0]; blo[kt][2*p][1] = r4[1];
            blo[kt][2*p+1][0] = r4[2]; blo[kt][2*p+1][1] = r4[3];
        }
    }
    grid_barrier();   // h(0) visible; W-frag reads done before H reuses the area

    float c_st = 0.0f;
    const float* xg_base = g_xg + (size_t)b * Gdim + (j0 + jj);

    for (int t = 0; t < Sdim; t++) {
        int cur = t & 1;
        float x_i = __ldg(xg_base + 0 * Hdim);
        float x_f = __ldg(xg_base + 1 * Hdim);
        float x_g = __ldg(xg_base + 2 * Hdim);
        float x_o = __ldg(xg_base + 3 * Hdim);

        // stage h(t-1) split: 2 x 32KB -> smem (barrier at loop end published it)
        const char* srchi = (const char*)g_hb_hi[cur];
        const char* srclo = (const char*)g_hb_lo[cur];
#pragma unroll
        for (int i = 0; i < 8; i++) {
            int idx = tid + i * 256;          // 0..2047 (16B chunks)
            int r = idx >> 6, ch = idx & 63;
            CP_ASYNC16(sHhi + r * RSTRIDE + ch * 16, srchi + idx * 16);
            CP_ASYNC16(sHlo + r * RSTRIDE + ch * 16, srclo + idx * 16);
        }
        CP_COMMIT();
        CP_WAIT0();
        __syncthreads();

        // MMA: [32 x 64-slice] x [64-slice x 32] partials
        float acc[2][4][4];
#pragma unroll
        for (int i = 0; i < 2; i++)
#pragma unroll
            for (int j = 0; j < 4; j++)
#pragma unroll
                for (int k = 0; k < 4; k++) acc[i][j][k] = 0.0f;

#pragma unroll
        for (int kt = 0; kt < 4; kt++) {
            int colb = kbase + kt * 16 + (tile >> 1) * 8;
            uint32_t ahi[2][4], alo[2][4];
#pragma unroll
            for (int mf = 0; mf < 2; mf++) {
                int row = mf * 16 + (tile & 1) * 8 + trow;
                ldm_x4(ahi[mf], sHhi + row * RSTRIDE + colb * 2);
                ldm_x4(alo[mf], sHlo + row * RSTRIDE + colb * 2);
            }
#pragma unroll
            for (int mf = 0; mf < 2; mf++)
#pragma unroll
                for (int nf = 0; nf < 4; nf++) {
                    mma_bf16(acc[mf][nf], ahi[mf], bhi[kt][nf]);
                    mma_bf16(acc[mf][nf], ahi[mf], blo[kt][nf]);
                    mma_bf16(acc[mf][nf], alo[mf], bhi[kt][nf]);
                }
        }

        // per-warp partials -> red[wid][m 0..31][n 0..31]
#pragma unroll
        for (int mf = 0; mf < 2; mf++)
#pragma unroll
            for (int nf = 0; nf < 4; nf++) {
                int row = mf * 16 + (lane >> 2);
                int col = nf * 8 + (lane & 3) * 2;
                float* p0 = red + ((wid * 32 + row) * RED_LEN + col);
                p0[0] = acc[mf][nf][0]; p0[1] = acc[mf][nf][1];
                float* p1 = red + ((wid * 32 + row + 8) * RED_LEN + col);
                p1[0] = acc[mf][nf][2]; p1[1] = acc[mf][nf][3];
            }
        __syncthreads();

        // all 256 threads: (b, jj) activation + state update
        {
            float di = x_i, df = x_f, dg = x_g, do_ = x_o;
#pragma unroll
            for (int w = 0; w < 8; w++) {
                const float* rr = red + (w * 32 + b) * RED_LEN;
                di  += rr[0 * 8 + jj];
                df  += rr[1 * 8 + jj];
                dg  += rr[2 * 8 + jj];
                do_ += rr[3 * 8 + jj];
            }
            float ig = 1.0f / (1.0f + __expf(-di));
            float fg = 1.0f / (1.0f + __expf(-df));
            float gg = tanhf(dg);
            float og = 1.0f / (1.0f + __expf(-do_));
            c_st = fg * c_st + ig * gg;
            float h = og * tanhf(c_st);

            __nv_bfloat16 hh = __float2bfloat16_rn(h);
            __nv_bfloat16 hl = __float2bfloat16_rn(h - __bfloat162float(hh));
            g_hb_hi[cur ^ 1][b * Hdim + j0 + jj] = hh;
            g_hb_lo[cur ^ 1][b * Hdim + j0 + jj] = hl;
            if (out_bsh) {
                hseq[((size_t)b * Sdim + t) * Hdim + j0 + jj] = h;
                if (hTo && t == Sdim - 1) {
                    hTo[b * Hdim + j0 + jj] = h;
                    cTo[b * Hdim + j0 + jj] = c_st;
                }
            } else {
                size_t r = ((size_t)t * Bdim + b) * Hdim + j0 + jj;
                g_h1hi[r] = hh;
                g_h1lo[r] = hl;
            }
        }
        grid_barrier();   // publishes h(t); isolates red / sH reuse

        xg_base += (size_t)Bdim * Gdim;
    }
}

// ---------------- launch ----------------
extern "C" void kernel_launch(void* const* d_in, const int* in_sizes, int n_in,
                              void* d_out, int out_size) {
    (void)in_sizes; (void)n_in;
    const float* X   = (const float*)d_in[0];
    const float* Wih = (const float*)d_in[1];
    const float* Whh = (const float*)d_in[2];
    const float* bih = (const float*)d_in[3];
    const float* bhh = (const float*)d_in[4];
    float* out = (float*)d_out;

    size_t ht_elems = (size_t)Bdim * Sdim * Hdim;
    float* hTo = nullptr; float* cTo = nullptr;
    if ((size_t)out_size >= ht_elems + 2 * (size_t)Bdim * Hdim) {
        hTo = out + ht_elems;
        cTo = hTo + (size_t)Bdim * Hdim;
    }

    const int smem_rec  = RED_OFF + 8 * 32 * RED_LEN * 4;   // 66560 + 33792 = 100352
    const int smem_gemm = 2 * STAGE_B;                      // 81920
    cudaFuncSetAttribute(lstm_recur_mma,
                         cudaFuncAttributeMaxDynamicSharedMemorySize, smem_rec);
    cudaFuncSetAttribute(gemm_mma_kernel,
                         cudaFuncAttributeMaxDynamicSharedMemorySize, smem_gemm);

    conv_w_kernel<<<2048, 256>>>(Wih);
    conv_x_kernel<<<32768, 256>>>(X);

    dim3 ggrid(Gdim / 128, (Sdim * Bdim) / 128);   // (16, 512)

    // Layer 0
    gemm_mma_kernel<<<ggrid, 256, smem_gemm>>>(0, 0, bih, bhh);
    lstm_recur_mma<<<NCTA_REC, 256, smem_rec>>>(Whh, nullptr, 0, nullptr, nullptr);
    // Layer 1
    gemm_mma_kernel<<<ggrid, 256, smem_gemm>>>(1, 1, bih + Gdim, bhh + Gdim);
    lstm_recur_mma<<<NCTA_REC, 256, smem_rec>>>(Whh + (size_t)Gdim * Hdim,
                                                out, 1, hTo, cTo);
}

// round 10
// speedup vs baseline: 1.0063x; 1.0038x over previous
#include <cuda_runtime.h>
#include <cuda_bf16.h>
#include <cstdint>

#define Sdim 2048
#define Bdim 32
#define Hdim 512
#define Gdim 2048   // 4*H
#define NCTA_REC 64

typedef unsigned long long ull;

// ---------------- scratch (module-load allocated) ----------------
__device__ float g_xg [(size_t)Sdim * Bdim * Gdim];               // [s*B+b][4H]
__device__ __align__(16) __nv_bfloat16 g_Ahi [(size_t)Sdim * Bdim * Hdim];
__device__ __align__(16) __nv_bfloat16 g_Alo [(size_t)Sdim * Bdim * Hdim];
__device__ __align__(16) __nv_bfloat16 g_h1hi[(size_t)Sdim * Bdim * Hdim];
__device__ __align__(16) __nv_bfloat16 g_h1lo[(size_t)Sdim * Bdim * Hdim];
__device__ __align__(16) __nv_bfloat16 g_Whi [2 * (size_t)Gdim * Hdim];
__device__ __align__(16) __nv_bfloat16 g_Wlo [2 * (size_t)Gdim * Hdim];
__device__ __align__(16) __nv_bfloat16 g_hb_hi[2][Bdim * Hdim];   // ping-pong h split
__device__ __align__(16) __nv_bfloat16 g_hb_lo[2][Bdim * Hdim];
__device__ unsigned g_cnt;
__device__ unsigned g_gen;

// ---------------- PTX helpers ----------------
__device__ __forceinline__ uint32_t smem_u32(const void* p) {
    uint32_t a;
    asm("{ .reg .u64 t; cvta.to.shared.u64 t, %1; cvt.u32.u64 %0, t; }" : "=r"(a) : "l"(p));
    return a;
}
#define CP_ASYNC16(dst, src) \
    asm volatile("cp.async.cg.shared.global [%0], [%1], 16;" :: "r"(dst), "l"(src))
#define CP_COMMIT() asm volatile("cp.async.commit_group;" ::: "memory")
#define CP_WAIT1()  asm volatile("cp.async.wait_group 1;" ::: "memory")
#define CP_WAIT0()  asm volatile("cp.async.wait_group 0;" ::: "memory")

__device__ __forceinline__ void ldm_x4(uint32_t* r, uint32_t addr) {
    asm volatile("ldmatrix.sync.aligned.m8n8.x4.shared.b16 {%0,%1,%2,%3}, [%4];"
                 : "=r"(r[0]), "=r"(r[1]), "=r"(r[2]), "=r"(r[3]) : "r"(addr));
}
__device__ __forceinline__ void mma_bf16(float* d, const uint32_t* a, const uint32_t* b) {
    asm volatile(
        "mma.sync.aligned.m16n8k16.row.col.f32.bf16.bf16.f32 "
        "{%0,%1,%2,%3}, {%4,%5,%6,%7}, {%8,%9}, {%0,%1,%2,%3};"
        : "+f"(d[0]), "+f"(d[1]), "+f"(d[2]), "+f"(d[3])
        : "r"(a[0]), "r"(a[1]), "r"(a[2]), "r"(a[3]), "r"(b[0]), "r"(b[1]));
}

// ---------------- grid barrier (validated R1/R4/R6; replay-safe) ----------------
__device__ __forceinline__ void grid_barrier() {
    __syncthreads();
    if (threadIdx.x == 0) {
        __threadfence();
        unsigned gen = *(volatile unsigned*)&g_gen;
        unsigned old = atomicAdd(&g_cnt, 1u);
        if (old == gridDim.x - 1) {
            atomicExch(&g_cnt, 0u);
            __threadfence();
            atomicAdd(&g_gen, 1u);
        } else {
            while (*(volatile unsigned*)&g_gen == gen) { __nanosleep(32); }
        }
        __threadfence();
    }
    __syncthreads();
}

// ---------------- fp32 -> bf16 hi/lo split ----------------
__device__ __forceinline__ void split4(float4 v, ull& hi, ull& lo) {
    union { __nv_bfloat16 h[4]; ull u; } H, L;
    float f[4] = {v.x, v.y, v.z, v.w};
#pragma unroll
    for (int i = 0; i < 4; i++) {
        __nv_bfloat16 a = __float2bfloat16_rn(f[i]);
        H.h[i] = a;
        L.h[i] = __float2bfloat16_rn(f[i] - __bfloat162float(a));
    }
    hi = H.u; lo = L.u;
}

// X[b][s][k] -> g_Ahi/g_Alo[(s*B+b)][k]
__global__ __launch_bounds__(256) void conv_x_kernel(const float* __restrict__ X) {
    size_t i = (size_t)blockIdx.x * 256 + threadIdx.x;
    int row = (int)(i >> 7);
    int c4  = (int)(i & 127);
    int b = row & 31, s = row >> 5;
    float4 v = __ldg((const float4*)(X + ((size_t)b * Sdim + s) * Hdim + c4 * 4));
    ull hi, lo;
    split4(v, hi, lo);
    *(ull*)(g_Ahi + (size_t)row * Hdim + c4 * 4) = hi;
    *(ull*)(g_Alo + (size_t)row * Hdim + c4 * 4) = lo;
}

// Wih[2][4H][H] -> g_Whi/g_Wlo
__global__ __launch_bounds__(256) void conv_w_kernel(const float* __restrict__ W) {
    size_t i = (size_t)blockIdx.x * 256 + threadIdx.x;
    float4 v = __ldg((const float4*)W + i);
    ull hi, lo;
    split4(v, hi, lo);
    *(ull*)(g_Whi + i * 4) = hi;
    *(ull*)(g_Wlo + i * 4) = lo;
}

// ---------------- mma.sync split-bf16 GEMM (validated R4) ----------------
#define TSTRIDE 80
#define MAT_B   (128 * TSTRIDE)
#define STAGE_B (4 * MAT_B)

__global__ __launch_bounds__(256, 1) void gemm_mma_kernel(
    int src_h1, int layer,
    const float* __restrict__ bih, const float* __restrict__ bhh)
{
    extern __shared__ char smem[];
    uint32_t sb = smem_u32(smem);
    int tid = threadIdx.x, wid = tid >> 5, lane = tid & 31;
    int col0 = blockIdx.x * 128;
    int row0 = blockIdx.y * 128;
    int wm = wid & 1, wn = wid >> 1;

    const __nv_bfloat16* a0p = (src_h1 ? g_h1hi : g_Ahi) + (size_t)row0 * Hdim;
    const __nv_bfloat16* a1p = (src_h1 ? g_h1lo : g_Alo) + (size_t)row0 * Hdim;
    const __nv_bfloat16* w0p = g_Whi + (size_t)layer * Gdim * Hdim + (size_t)col0 * Hdim;
    const __nv_bfloat16* w1p = g_Wlo + (size_t)layer * Gdim * Hdim + (size_t)col0 * Hdim;

    int ldr  = tid >> 2;
    int ldkc = tid & 3;

#define PREFETCH(stg, k0)                                                         \
    do {                                                                          \
        _Pragma("unroll")                                                         \
        for (int m = 0; m < 4; m++) {                                             \
            const __nv_bfloat16* mp = (m == 0 ? a0p : m == 1 ? a1p :              \
                                       m == 2 ? w0p : w1p);                       \
            _Pragma("unroll")                                                     \
            for (int i = 0; i < 2; i++) {                                         \
                int r = ldr + i * 64;                                             \
                uint32_t dst = sb + (stg) * STAGE_B + m * MAT_B +                 \
                               r * TSTRIDE + ldkc * 16;                           \
                const void* srcp = mp + (size_t)r * Hdim + (k0) + ldkc * 8;       \
                CP_ASYNC16(dst, srcp);                                            \
            }                                                                     \
        }                                                                         \
        CP_COMMIT();                                                              \
    } while (0)

    float acc[4][4][4];
#pragma unroll
    for (int i = 0; i < 4; i++)
#pragma unroll
        for (int j = 0; j < 4; j++)
#pragma unroll
            for (int k = 0; k < 4; k++) acc[i][j][k] = 0.0f;

    PREFETCH(0, 0);
    PREFETCH(1, 32);

    int tile = lane >> 3, trow = lane & 7;

    for (int kt = 0; kt < 16; kt++) {
        if (kt == 15) CP_WAIT0(); else CP_WAIT1();
        __syncthreads();
        uint32_t base = sb + (kt & 1) * STAGE_B;

#pragma unroll
        for (int ks = 0; ks < 2; ks++) {
            uint32_t ahi[4][4], alo[4][4];
#pragma unroll
            for (int mf = 0; mf < 4; mf++) {
                int row = wm * 64 + mf * 16 + (tile & 1) * 8 + trow;
                int col = ks * 16 + (tile >> 1) * 8;
                ldm_x4(ahi[mf], base + 0 * MAT_B + row * TSTRIDE + col * 2);
                ldm_x4(alo[mf], base + 1 * MAT_B + row * TSTRIDE + col * 2);
            }
            uint32_t bhi[4][2], blo[4][2];
#pragma unroll
            for (int p = 0; p < 2; p++) {
                int rn = wn * 32 + p * 16 + (tile >> 1) * 8 + trow;
                int ck = ks * 16 + (tile & 1) * 8;
                uint32_t r4[4];
                ldm_x4(r4, base + 2 * MAT_B + rn * TSTRIDE + ck * 2);
                bhi[2*p][0] = r4[0]; bhi[2*p][1] = r4[1];
                bhi[2*p+1][0] = r4[2]; bhi[2*p+1][1] = r4[3];
                ldm_x4(r4, base + 3 * MAT_B + rn * TSTRIDE + ck * 2);
                blo[2*p][0] = r4[0]; blo[2*p][1] = r4[1];
                blo[2*p+1][0] = r4[2]; blo[2*p+1][1] = r4[3];
            }
#pragma unroll
            for (int mf = 0; mf < 4; mf++)
#pragma unroll
                for (int nf = 0; nf < 4; nf++) {
                    mma_bf16(acc[mf][nf], ahi[mf], bhi[nf]);
                    mma_bf16(acc[mf][nf], ahi[mf], blo[nf]);
                    mma_bf16(acc[mf][nf], alo[mf], bhi[nf]);
                }
        }
        __syncthreads();
        if (kt < 14) PREFETCH(kt & 1, (kt + 2) * 32);
    }

#pragma unroll
    for (int mf = 0; mf < 4; mf++) {
        int r0 = row0 + wm * 64 + mf * 16 + (lane >> 2);
#pragma unroll
        for (int nf = 0; nf < 4; nf++) {
            int cb = col0 + wn * 32 + nf * 8 + 2 * (lane & 3);
            float b0v = __ldg(&bih[cb])     + __ldg(&bhh[cb]);
            float b1v = __ldg(&bih[cb + 1]) + __ldg(&bhh[cb + 1]);
            *(float2*)&g_xg[(size_t)r0 * Gdim + cb] =
                make_float2(acc[mf][nf][0] + b0v, acc[mf][nf][1] + b1v);
            *(float2*)&g_xg[(size_t)(r0 + 8) * Gdim + cb] =
                make_float2(acc[mf][nf][2] + b0v, acc[mf][nf][3] + b1v);
        }
    }
#undef PREFETCH
}

// ---------------- persistent recurrence on tensor cores ----------------
// 64 CTAs x 256 threads. CTA owns 8 hidden units (32 gate cols).
// Whh B-frags in registers (split bf16); h staged split via cp.async each step.
// 8-warp k-split (64 each); smem reduction; 256 threads do activations.
#define RSTRIDE 1040                 // bytes per smem bf16 row of 512 (+8 pad)
#define RED_OFF (64 * RSTRIDE)       // 66560
#define RED_LEN 33                   // floats per red row

__global__ __launch_bounds__(256, 1) void lstm_recur_mma(
    const float* __restrict__ Whh, float* __restrict__ hseq,
    int out_bsh, float* __restrict__ hTo, float* __restrict__ cTo)
{
    extern __shared__ char sm[];
    uint32_t sb = smem_u32(sm);
    uint32_t sHhi = sb;                       // [32 rows] (also W-hi staging at init)
    uint32_t sHlo = sb + 32 * RSTRIDE;        // [32 rows] (also W-lo staging at init)
    float* red = (float*)(sm + RED_OFF);      // [8][32][RED_LEN]

    int tid = threadIdx.x, wid = tid >> 5, lane = tid & 31;
    int b  = tid & 31;
    int jj = tid >> 5;          // 0..7: hidden unit within CTA
    int j0 = blockIdx.x * 8;

    // stage Whh (split bf16) into the H area: row r = q*8 + j  <-  Whh[q*512 + j0 + j]
    for (int idx = tid; idx < 32 * 128; idx += 256) {
        int r = idx >> 7, c4 = idx & 127;
        int q = r >> 3, j = r & 7;
        float4 v = __ldg((const float4*)(Whh + (size_t)(q * Hdim + j0 + j) * Hdim + c4 * 4));
        ull hi, lo;
        split4(v, hi, lo);
        *(ull*)(sm + r * RSTRIDE + c4 * 8) = hi;
        *(ull*)(sm + 32 * RSTRIDE + r * RSTRIDE + c4 * 8) = lo;
    }
    // h(0) = 0 (64 CTAs x 256 threads cover all 32x512)
    g_hb_hi[0][b * Hdim + j0 + jj] = __float2bfloat16(0.0f);
    g_hb_lo[0][b * Hdim + j0 + jj] = __float2bfloat16(0.0f);
    __syncthreads();

    // preload B fragments: warp w owns k in [w*64, w*64+64); N=32 gate cols
    int kbase = wid * 64;
    int tile = lane >> 3, trow = lane & 7;
    uint32_t bhi[4][4][2], blo[4][4][2];
#pragma unroll
    for (int kt = 0; kt < 4; kt++) {
#pragma unroll
        for (int p = 0; p < 2; p++) {
            int rn = p * 16 + (tile >> 1) * 8 + trow;
            int ck = kbase + kt * 16 + (tile & 1) * 8;
            uint32_t r4[4];
            ldm_x4(r4, sHhi + rn * RSTRIDE + ck * 2);
            bhi[kt][2*p][0] = r4[0]; bhi[kt][2*p][1] = r4[1];
            bhi[kt][2*p+1][0] = r4[2]; bhi[kt][2*p+1][1] = r4[3];
            ldm_x4(r4, sHlo + rn * RSTRIDE + ck * 2);
            blo[kt][2*p][0] = r4[0]; blo[kt][2*p][1] = r4[1];
            blo[kt][2*p+1][0] = r4[2]; blo[kt][2*p+1][1] = r4[3];
        }
    }
    grid_barrier();   // h(0) visible; W-frag reads done before H reuses the area

    float c_st = 0.0f;
    const float* xg_base = g_xg + (size_t)b * Gdim + (j0 + jj);

    for (int t = 0; t < Sdim; t++) {
        int cur = t & 1;
        float x_i = __ldg(xg_base + 0 * Hdim);
        float x_f = __ldg(xg_base + 1 * Hdim);
        float x_g = __ldg(xg_base + 2 * Hdim);
        float x_o = __ldg(xg_base + 3 * Hdim);

        // stage h(t-1) split: 2 x 32KB -> smem (barrier at loop end published it)
        const char* srchi = (const char*)g_hb_hi[cur];
        const char* srclo = (const char*)g_hb_lo[cur];
#pragma unroll
        for (int i = 0; i < 8; i++) {
            int idx = tid + i * 256;          // 0..2047 (16B chunks)
            int r = idx >> 6, ch = idx & 63;
            CP_ASYNC16(sHhi + r * RSTRIDE + ch * 16, srchi + idx * 16);
            CP_ASYNC16(sHlo + r * RSTRIDE + ch * 16, srclo + idx * 16);
        }
        CP_COMMIT();
        CP_WAIT0();
        __syncthreads();

        // MMA: [32 x 64-slice] x [64-slice x 32] partials
        float acc[2][4][4];
#pragma unroll
        for (int i = 0; i < 2; i++)
#pragma unroll
            for (int j = 0; j < 4; j++)
#pragma unroll
                for (int k = 0; k < 4; k++) acc[i][j][k] = 0.0f;

#pragma unroll
        for (int kt = 0; kt < 4; kt++) {
            int colb = kbase + kt * 16 + (tile >> 1) * 8;
            uint32_t ahi[2][4], alo[2][4];
#pragma unroll
            for (int mf = 0; mf < 2; mf++) {
                int row = mf * 16 + (tile & 1) * 8 + trow;
                ldm_x4(ahi[mf], sHhi + row * RSTRIDE + colb * 2);
                ldm_x4(alo[mf], sHlo + row * RSTRIDE + colb * 2);
            }
#pragma unroll
            for (int mf = 0; mf < 2; mf++)
#pragma unroll
                for (int nf = 0; nf < 4; nf++) {
                    mma_bf16(acc[mf][nf], ahi[mf], bhi[kt][nf]);
                    mma_bf16(acc[mf][nf], ahi[mf], blo[kt][nf]);
                    mma_bf16(acc[mf][nf], alo[mf], bhi[kt][nf]);
                }
        }

        // per-warp partials -> red[wid][m 0..31][n 0..31]
#pragma unroll
        for (int mf = 0; mf < 2; mf++)
#pragma unroll
            for (int nf = 0; nf < 4; nf++) {
                int row = mf * 16 + (lane >> 2);
                int col = nf * 8 + (lane & 3) * 2;
                float* p0 = red + ((wid * 32 + row) * RED_LEN + col);
                p0[0] = acc[mf][nf][0]; p0[1] = acc[mf][nf][1];
                float* p1 = red + ((wid * 32 + row + 8) * RED_LEN + col);
                p1[0] = acc[mf][nf][2]; p1[1] = acc[mf][nf][3];
            }
        __syncthreads();

        // all 256 threads: (b, jj) activation + state update
        {
            float di = x_i, df = x_f, dg = x_g, do_ = x_o;
#pragma unroll
            for (int w = 0; w < 8; w++) {
                const float* rr = red + (w * 32 + b) * RED_LEN;
                di  += rr[0 * 8 + jj];
                df  += rr[1 * 8 + jj];
                dg  += rr[2 * 8 + jj];
                do_ += rr[3 * 8 + jj];
            }
            float ig = 1.0f / (1.0f + __expf(-di));
            float fg = 1.0f / (1.0f + __expf(-df));
            float gg = tanhf(dg);
            float og = 1.0f / (1.0f + __expf(-do_));
            c_st = fg * c_st + ig * gg;
            float h = og * tanhf(c_st);

            __nv_bfloat16 hh = __float2bfloat16_rn(h);
            __nv_bfloat16 hl = __float2bfloat16_rn(h - __bfloat162float(hh));
            g_hb_hi[cur ^ 1][b * Hdim + j0 + jj] = hh;
            g_hb_lo[cur ^ 1][b * Hdim + j0 + jj] = hl;
            if (out_bsh) {
                hseq[((size_t)b * Sdim + t) * Hdim + j0 + jj] = h;
                if (hTo && t == Sdim - 1) {
                    hTo[b * Hdim + j0 + jj] = h;
                    cTo[b * Hdim + j0 + jj] = c_st;
                }
            } else {
                size_t r = ((size_t)t * Bdim + b) * Hdim + j0 + jj;
                g_h1hi[r] = hh;
                g_h1lo[r] = hl;
            }
        }
        grid_barrier();   // publishes h(t); isolates red / sH reuse

        xg_base += (size_t)Bdim * Gdim;
    }
}

// ---------------- launch ----------------
extern "C" void kernel_launch(void* const* d_in, const int* in_sizes, int n_in,
                              void* d_out, int out_size) {
    (void)in_sizes; (void)n_in;
    const float* X   = (const float*)d_in[0];
    const float* Wih = (const float*)d_in[1];
    const float* Whh = (const float*)d_in[2];
    const float* bih = (const float*)d_in[3];
    const float* bhh = (const float*)d_in[4];
    float* out = (float*)d_out;

    size_t ht_elems = (size_t)Bdim * Sdim * Hdim;
    float* hTo = nullptr; float* cTo = nullptr;
    if ((size_t)out_size >= ht_elems + 2 * (size_t)Bdim * Hdim) {
        hTo = out + ht_elems;
        cTo = hTo + (size_t)Bdim * Hdim;
    }

    const int smem_rec  = RED_OFF + 8 * 32 * RED_LEN * 4;   // 66560 + 33792 = 100352
    const int smem_gemm = 2 * STAGE_B;                      // 81920
    cudaFuncSetAttribute(lstm_recur_mma,
                         cudaFuncAttributeMaxDynamicSharedMemorySize, smem_rec);
    cudaFuncSetAttribute(gemm_mma_kernel,
                         cudaFuncAttributeMaxDynamicSharedMemorySize, smem_gemm);

    conv_w_kernel<<<2048, 256>>>(Wih);
    conv_x_kernel<<<32768, 256>>>(X);

    dim3 ggrid(Gdim / 128, (Sdim * Bdim) / 128);   // (16, 512)

    // Layer 0
    gemm_mma_kernel<<<ggrid, 256, smem_gemm>>>(0, 0, bih, bhh);
    lstm_recur_mma<<<NCTA_REC, 256, smem_rec>>>(Whh, nullptr, 0, nullptr, nullptr);
    // Layer 1
    gemm_mma_kernel<<<ggrid, 256, smem_gemm>>>(1, 1, bih + Gdim, bhh + Gdim);
    lstm_recur_mma<<<NCTA_REC, 256, smem_rec>>>(Whh + (size_t)Gdim * Hdim,
                                                out, 1, hTo, cTo);
}